// round 15
// baseline (speedup 1.0000x reference)
#include <cuda_runtime.h>
#include <cuda.h>
#include <cuda_bf16.h>
#include <cstdint>
#include <math.h>

#define B_ 8
#define T_ 4096
#define D_ 1024
#define H_ 64
#define BT_ (B_*T_)   // 32768

#if defined(__CUDA_ARCH_FEAT_SM103_ALL) || defined(__CUDA_ARCH_FEAT_SM100_ALL)
#define HAS_TC 1
#else
#define HAS_TC 0
#endif

// ---------------- scratch ----------------
__device__ __nv_bfloat16 g_xn [(size_t)BT_*D_];
__device__ __nv_bfloat16 g_xbz[(size_t)BT_*2048];
__device__ __nv_bfloat16 g_xc [(size_t)BT_*D_];
__device__ __nv_bfloat16 g_projd[(size_t)BT_*1024];
__device__ float         g_a  [(size_t)512*4096];
__device__ float         g_bu [(size_t)512*4096];
__device__ __nv_bfloat16 g_h2 [(size_t)512*4096];
__device__ __nv_bfloat16 g_h  [(size_t)BT_*H_];
__device__ __nv_bfloat16 g_u  [(size_t)BT_*D_];
__device__ __nv_bfloat16 g_Wa [(size_t)2048*1024];
__device__ __nv_bfloat16 g_Wb [(size_t)1152*1024];
__device__ __nv_bfloat16 g_Wc [(size_t)1024*64];
__device__ __nv_bfloat16 g_Wd [(size_t)1024*1024];

// ---------------- helpers ----------------
__device__ __forceinline__ float siluf(float v){ return v / (1.f + __expf(-v)); }
__device__ __forceinline__ float softplusf(float v){ return (v > 20.f) ? v : log1pf(expf(v)); }
__device__ __forceinline__ float clipf(float v){ return fminf(fmaxf(v, -20.f), 20.f); }

__device__ __forceinline__ void mbar_wait(uint32_t addr, uint32_t parity){
    asm volatile(
        "{\n\t.reg .pred P;\n"
        "W_%=:\n\t"
        "mbarrier.try_wait.parity.shared.b64 P, [%0], %1;\n\t"
        "@P bra D_%=;\n\t"
        "bra W_%=;\n"
        "D_%=:\n\t}"
        :: "r"(addr), "r"(parity) : "memory");
}
__device__ __forceinline__ void mbar_init(uint32_t addr, uint32_t cnt){
    asm volatile("mbarrier.init.shared.b64 [%0], %1;" :: "r"(addr), "r"(cnt) : "memory");
}
__device__ __forceinline__ void mbar_expect_tx(uint32_t addr, uint32_t bytes){
    asm volatile("mbarrier.arrive.expect_tx.shared.b64 _, [%0], %1;" :: "r"(addr), "r"(bytes) : "memory");
}
__device__ __forceinline__ void fr_arrive_rank0(uint32_t addr){
    asm volatile(
        "{\n\t.reg .b32 ra;\n\t"
        "mapa.shared::cluster.u32 ra, %0, 0;\n\t"
        "mbarrier.arrive.shared::cluster.b64 _, [ra];\n\t}"
        :: "r"(addr) : "memory");
}
__device__ __forceinline__ void cluster_sync_(){
    asm volatile("barrier.cluster.arrive.aligned;" ::: "memory");
    asm volatile("barrier.cluster.wait.aligned;" ::: "memory");
}
__device__ __forceinline__ uint32_t ctarank(){
    uint32_t r; asm("mov.u32 %0, %%cluster_ctarank;" : "=r"(r)); return r;
}
__device__ __forceinline__ void tma2d(uint32_t dst, const void* map, int x, int y, uint32_t mbar){
#if HAS_TC
    asm volatile(
        "cp.async.bulk.tensor.2d.shared::cta.global.tile.mbarrier::complete_tx::bytes "
        "[%0], [%1, {%2, %3}], [%4];"
        :: "r"(dst), "l"(map), "r"(x), "r"(y), "r"(mbar) : "memory");
#endif
}
__device__ __forceinline__ void tma2d_mc(uint32_t dst, const void* map, int x, int y, uint32_t mbar){
#if HAS_TC
    asm volatile(
        "cp.async.bulk.tensor.2d.shared::cluster.global.tile.mbarrier::complete_tx::bytes.multicast::cluster "
        "[%0], [%1, {%2, %3}], [%4], %5;"
        :: "r"(dst), "l"(map), "r"(x), "r"(y), "r"(mbar), "h"((uint16_t)3) : "memory");
#endif
}
__device__ __forceinline__ uint64_t sdesc(uint32_t a){
    return ((uint64_t)2 << 61) | ((uint64_t)1 << 46) | ((uint64_t)64 << 32)
         | ((uint64_t)1 << 16) | ((a >> 4) & 0x3FFF);
}
__device__ __forceinline__ void mma_f16_ss(uint32_t dt, uint64_t ad, uint64_t bd,
                                           uint32_t idesc, uint32_t en){
#if HAS_TC
    asm volatile(
        "{\n\t.reg .pred p;\n\t"
        "setp.ne.u32 p, %5, 0;\n\t"
        "tcgen05.mma.cta_group::1.kind::f16 [%0], %1, %2, %3, {%4,%4,%4,%4}, p;\n\t}"
        :: "r"(dt), "l"(ad), "l"(bd), "r"(idesc), "r"(0u), "r"(en) : "memory");
#endif
}
__device__ __forceinline__ void ldtm32(uint32_t addr, uint32_t* r){
#if HAS_TC
    asm volatile(
        "tcgen05.ld.sync.aligned.32x32b.x32.b32 "
        "{%0,%1,%2,%3,%4,%5,%6,%7,%8,%9,%10,%11,%12,%13,%14,%15,"
        "%16,%17,%18,%19,%20,%21,%22,%23,%24,%25,%26,%27,%28,%29,%30,%31}, [%32];"
        : "=r"(r[0]),"=r"(r[1]),"=r"(r[2]),"=r"(r[3]),"=r"(r[4]),"=r"(r[5]),"=r"(r[6]),"=r"(r[7]),
          "=r"(r[8]),"=r"(r[9]),"=r"(r[10]),"=r"(r[11]),"=r"(r[12]),"=r"(r[13]),"=r"(r[14]),"=r"(r[15]),
          "=r"(r[16]),"=r"(r[17]),"=r"(r[18]),"=r"(r[19]),"=r"(r[20]),"=r"(r[21]),"=r"(r[22]),"=r"(r[23]),
          "=r"(r[24]),"=r"(r[25]),"=r"(r[26]),"=r"(r[27]),"=r"(r[28]),"=r"(r[29]),"=r"(r[30]),"=r"(r[31])
        : "r"(addr));
#else
    #pragma unroll
    for (int i = 0; i < 32; i++) r[i] = 0u;
    (void)addr;
#endif
}
__device__ __forceinline__ void tc_alloc(uint32_t smem_addr, uint32_t ncols){
#if HAS_TC
    asm volatile("tcgen05.alloc.cta_group::1.sync.aligned.shared::cta.b32 [%0], %1;"
                 :: "r"(smem_addr), "r"(ncols) : "memory");
#endif
}
__device__ __forceinline__ void tc_dealloc(uint32_t tmem, uint32_t ncols){
#if HAS_TC
    asm volatile("tcgen05.relinquish_alloc_permit.cta_group::1.sync.aligned;");
    asm volatile("tcgen05.dealloc.cta_group::1.sync.aligned.b32 %0, %1;" :: "r"(tmem), "r"(ncols));
#endif
}
__device__ __forceinline__ void tc_commit(uint32_t mbar){
#if HAS_TC
    asm volatile("tcgen05.commit.cta_group::1.mbarrier::arrive::one.shared::cluster.b64 [%0];"
                 :: "r"(mbar) : "memory");
#endif
}
__device__ __forceinline__ void tc_fence_after(){
#if HAS_TC
    asm volatile("tcgen05.fence::after_thread_sync;" ::: "memory");
#endif
}
__device__ __forceinline__ void tc_wait_ld(){
#if HAS_TC
    asm volatile("tcgen05.wait::ld.sync.aligned;" ::: "memory");
#endif
}

// ---------------- weight conversion ----------------
__global__ void convert_wa(const float* __restrict__ W1, const float* __restrict__ W2){
    int i = blockIdx.x * blockDim.x + threadIdx.x;
    g_Wa[i] = __float2bfloat16(i < 1048576 ? W1[i] : W2[i - 1048576]);
}
__global__ void convert_wrest(const float* __restrict__ dwp, const float* __restrict__ Bwp,
                              const float* __restrict__ Dwp, const float* __restrict__ Cwp,
                              const float* __restrict__ Wlastp){
    int i = blockIdx.x * blockDim.x + threadIdx.x;
    const int NWb = 1152*1024, NWc = 1024*64, NWd = 1024*1024;
    if (i < NWb){
        float v = (i < 65536) ? dwp[i] : (i < 131072) ? Bwp[i - 65536] : Dwp[i - 131072];
        g_Wb[i] = __float2bfloat16(v);
    } else if (i < NWb + NWc){
        g_Wc[i - NWb] = __float2bfloat16(Cwp[i - NWb]);
    } else if (i < NWb + NWc + NWd){
        g_Wd[i - NWb - NWc] = __float2bfloat16(Wlastp[i - NWb - NWc]);
    }
}

// ---------------- RMSNorm ----------------
__global__ void rmsnorm_kernel(const float* __restrict__ x, const float* __restrict__ w){
    __shared__ float ws[8];
    int m = blockIdx.x, tid = threadIdx.x;
    float4 v = ((const float4*)(x + (size_t)m * D_))[tid];
    float ss = v.x*v.x + v.y*v.y + v.z*v.z + v.w*v.w;
    #pragma unroll
    for (int d = 16; d; d >>= 1) ss += __shfl_xor_sync(0xffffffffu, ss, d);
    if ((tid & 31) == 0) ws[tid >> 5] = ss;
    __syncthreads();
    if (tid == 0){ float s = 0.f; for (int i = 0; i < 8; i++) s += ws[i]; ws[0] = s; }
    __syncthreads();
    float scale = rsqrtf(ws[0] * (1.f / D_) + 1.1920928955078125e-07f);
    float4 wv = ((const float4*)w)[tid];
    __nv_bfloat162 p0 = __floats2bfloat162_rn(v.x*scale*wv.x, v.y*scale*wv.y);
    __nv_bfloat162 p1 = __floats2bfloat162_rn(v.z*scale*wv.z, v.w*scale*wv.w);
    __nv_bfloat162* dst = (__nv_bfloat162*)(g_xn + (size_t)m * D_) + tid * 2;
    dst[0] = p0; dst[1] = p1;
}

// ---------------- causal depthwise conv (k=3) + SiLU ----------------
__global__ void conv_silu_kernel(const float* __restrict__ conv_w, const float* __restrict__ conv_b){
    int idx = blockIdx.x * blockDim.x + threadIdx.x;
    int d2 = idx & 511;
    int rest = idx >> 9;
    int t8 = (rest & 511) * 8;
    int b = rest >> 9;
    int d = d2 * 2;
    __nv_bfloat162 zero2; zero2.x = __float2bfloat16(0.f); zero2.y = __float2bfloat16(0.f);
    __nv_bfloat162 v[10];
    #pragma unroll
    for (int i = 0; i < 10; i++){
        int t = t8 - 2 + i;
        v[i] = (t >= 0) ? *(const __nv_bfloat162*)(g_xbz + ((size_t)b*T_ + t)*2048 + d) : zero2;
    }
    float w00 = conv_w[d*3+0], w01 = conv_w[d*3+1], w02 = conv_w[d*3+2];
    float w10 = conv_w[d*3+3], w11 = conv_w[d*3+4], w12 = conv_w[d*3+5];
    float b0 = conv_b[d], b1 = conv_b[d+1];
    #pragma unroll
    for (int k = 0; k < 8; k++){
        float r0 = __bfloat162float(v[k].x)*w00 + __bfloat162float(v[k+1].x)*w01
                 + __bfloat162float(v[k+2].x)*w02 + b0;
        float r1 = __bfloat162float(v[k].y)*w10 + __bfloat162float(v[k+1].y)*w11
                 + __bfloat162float(v[k+2].y)*w12 + b1;
        *(__nv_bfloat162*)(g_xc + ((size_t)b*T_ + t8 + k)*1024 + d) =
            __floats2bfloat162_rn(siluf(r0), siluf(r1));
    }
}

// ---------------- block-parallel scan ----------------
__device__ __forceinline__ float block_excl_prefix(float total, float* wsum, int tid){
    __syncthreads();
    int lane = tid & 31, wid = tid >> 5;
    float v = total;
    #pragma unroll
    for (int d = 1; d < 32; d <<= 1){
        float o = __shfl_up_sync(0xffffffffu, v, d);
        if (lane >= d) v += o;
    }
    if (lane == 31) wsum[wid] = v;
    __syncthreads();
    if (tid == 0){
        float s = 0.f;
        for (int i = 0; i < 16; i++){ float t = wsum[i]; wsum[i] = s; s += t; }
    }
    __syncthreads();
    return wsum[wid] + v - total;
}

__global__ void scan_kernel(){
    __shared__ float wsum[16];
    int bh = blockIdx.x;
    int tid = threadIdx.x;
    size_t base = (size_t)bh * 4096 + tid * 8;
    float av[8], bv[8], ev[8], cv[8];
    {
        float4 a0 = *(const float4*)(g_a + base);
        float4 a1 = *(const float4*)(g_a + base + 4);
        av[0]=a0.x; av[1]=a0.y; av[2]=a0.z; av[3]=a0.w;
        av[4]=a1.x; av[5]=a1.y; av[6]=a1.z; av[7]=a1.w;
        float4 b0 = *(const float4*)(g_bu + base);
        float4 b1 = *(const float4*)(g_bu + base + 4);
        bv[0]=b0.x; bv[1]=b0.y; bv[2]=b0.z; bv[3]=b0.w;
        bv[4]=b1.x; bv[5]=b1.y; bv[6]=b1.z; bv[7]=b1.w;
    }
    float s = 0.f;
    #pragma unroll
    for (int i = 0; i < 8; i++){ s += av[i]; av[i] = s; }
    float pa = block_excl_prefix(av[7], wsum, tid);
    #pragma unroll
    for (int i = 0; i < 8; i++){
        float S = pa + av[i];
        float Sprev = pa + (i ? av[i-1] : 0.f);
        ev[i] = expf(clipf(S));
        cv[i] = bv[i] * expf(-clipf(Sprev));
    }
    s = 0.f;
    #pragma unroll
    for (int i = 0; i < 8; i++){ s += cv[i]; cv[i] = s; }
    float pb = block_excl_prefix(cv[7], wsum, tid);
    uint32_t p[4];
    #pragma unroll
    for (int i = 0; i < 4; i++){
        __nv_bfloat162 t2 = __floats2bfloat162_rn(ev[2*i] * (pb + cv[2*i]),
                                                  ev[2*i+1] * (pb + cv[2*i+1]));
        p[i] = *(uint32_t*)&t2;
    }
    *(uint4*)(g_h2 + base) = make_uint4(p[0], p[1], p[2], p[3]);
}

// ---------------- [bh][t] -> token-major transpose ----------------
__global__ void htrans_kernel(){
    __shared__ __nv_bfloat16 sm[64][80];
    int blk = blockIdx.x;
    int b = blk >> 6;
    int t0 = (blk & 63) << 6;
    for (int i = threadIdx.x; i < 512; i += 256){
        int h = i >> 3, c = i & 7;
        uint4 v = *(const uint4*)(g_h2 + ((size_t)(b*64 + h))*4096 + t0 + c*8);
        __nv_bfloat16 tmp[8];
        *(uint4*)tmp = v;
        #pragma unroll
        for (int q = 0; q < 8; q++) sm[c*8 + q][h] = tmp[q];
    }
    __syncthreads();
    for (int i = threadIdx.x; i < 512; i += 256){
        int t = i >> 3, hc = i & 7;
        uint4 v = *(uint4*)&sm[t][hc*8];
        *(uint4*)(g_h + ((size_t)(b*T_ + t0 + t))*64 + hc*8) = v;
    }
}

// ---------------- cluster-2 multicast GEMM: M128 x N<=256, NST=4, non-blocking ----------------
// CTAs (y even/odd) share the W tile via TMA multicast. EPI 0: bf16 -> g_xbz; EPI 3: +res -> out.
template<int EPI, int KDIM, int NTILE>
__global__ void __launch_bounds__(256, 1) __cluster_dims__(1, 2, 1) gemm_mc(
    const __grid_constant__ CUtensorMap mA,
    const __grid_constant__ CUtensorMap mW,
    const float* __restrict__ xres, float* __restrict__ outp)
{
    extern __shared__ __align__(1024) char smem_raw[];
    constexpr int NSC = KDIM / 64;
    constexpr int STAGE = 16384 + NTILE * 128;        // A(128x64) 16KB + W
    constexpr int NST = 4;
    constexpr uint32_t STBYTES = (uint32_t)STAGE;
    constexpr uint32_t IDESC = (1u<<4) | (1u<<7) | (1u<<10) | ((NTILE/8u)<<17) | (8u<<24);
    const int tid = threadIdx.x, lane = tid & 31, warp = tid >> 5;
    const int m0 = blockIdx.y * 128;
    const int n0 = blockIdx.x * NTILE;
    const uint32_t sbase = (uint32_t)__cvta_generic_to_shared(smem_raw);
    const uint32_t mb_wf = sbase + 16;
    const uint32_t mb_mm = sbase + 48;
    const uint32_t mb_fr = sbase + 80;
    const uint32_t rank = ctarank();

    if (warp == 0) tc_alloc(sbase, 256u);
    if (tid == 0){
        #pragma unroll
        for (int s = 0; s < NST; s++){
            mbar_init(mb_wf + 8*s, 1);
            mbar_init(mb_mm + 8*s, 1);
            mbar_init(mb_fr + 8*s, 2);
        }
    }
    __syncthreads();
    cluster_sync_();                                   // barriers visible before multicast
    uint32_t tmem;
    asm volatile("ld.shared.b32 %0, [%1];" : "=r"(tmem) : "r"(sbase));

    if (tid == 0){
        auto loadA = [&](int j){
            int s = j & 3;
            mbar_expect_tx(mb_wf + 8*s, STBYTES);
            tma2d(sbase + 1024 + (uint32_t)s * STAGE, (const void*)&mA, j*64, m0, mb_wf + 8*s);
        };
        auto loadW = [&](int j){
            int s = j & 3;
            uint32_t wb = sbase + 1024 + (uint32_t)s * STAGE + 16384;
            #pragma unroll
            for (int c = 0; c < NTILE; c += 64)
                tma2d_mc(wb + (uint32_t)c*128, (const void*)&mW, j*64, n0 + c, mb_wf + 8*s);
        };
        const int P = (NSC < 3) ? NSC : 3;
        for (int s = 0; s < P; s++) loadA(s);
        if (rank == 0) for (int s = 0; s < P; s++) loadW(s);

        for (int j = 0; j < NSC; j++){
            const int s = j & 3;
            mbar_wait(mb_wf + 8*s, (j >> 2) & 1);
            uint32_t ab = sbase + 1024 + (uint32_t)s * STAGE;
            uint64_t ad = sdesc(ab), bd = sdesc(ab + 16384);
            #pragma unroll
            for (int ks = 0; ks < 4; ks++)
                mma_f16_ss(tmem, ad + ks*2, bd + ks*2, IDESC, (j == 0 && ks == 0) ? 0u : 1u);
            tc_commit(mb_mm + 8*s);
            const int nl = j + 3;
            if (nl < NSC){
                if (j >= 1){
                    const int ps = (j-1) & 3;
                    const uint32_t pp = ((j-1) >> 2) & 1;
                    mbar_wait(mb_mm + 8*ps, pp);       // own MMA(j-1) done (long ago)
                    fr_arrive_rank0(mb_fr + 8*ps);     // tell leader slot is free
                    if (rank == 0) mbar_wait(mb_fr + 8*ps, pp);   // both CTAs free
                }
                loadA(nl);
                if (rank == 0) loadW(nl);
            }
        }
        mbar_wait(mb_mm + 8*((NSC-1) & 3), ((NSC-1) >> 2) & 1);
    }
    __syncthreads();
    tc_fence_after();

    // ---- epilogue: warps 0-3 rows, warp halves split N ----
    {
        const int rowgrp = warp & 3;
        const int half   = warp >> 2;
        const int m      = m0 + rowgrp * 32 + lane;
        const uint32_t woff = (uint32_t)rowgrp << 21;
        constexpr int GPW = NTILE / 64;
        uint32_t bufs[2][32];
        ldtm32(tmem + woff + half * (NTILE/2), bufs[0]);
        #pragma unroll
        for (int g = 0; g < GPW; g++){
            tc_wait_ld();
            if (g + 1 < GPW) ldtm32(tmem + woff + half*(NTILE/2) + (g+1)*32, bufs[(g+1) & 1]);
            const uint32_t* r32 = bufs[g & 1];
            const int nb = n0 + half*(NTILE/2) + g*32;
            #pragma unroll
            for (int q = 0; q < 4; q++){
                if (EPI == 0){
                    uint32_t p[4];
                    #pragma unroll
                    for (int i = 0; i < 4; i++){
                        __nv_bfloat162 t2 = __floats2bfloat162_rn(
                            __uint_as_float(r32[q*8 + 2*i]), __uint_as_float(r32[q*8 + 2*i + 1]));
                        p[i] = *(uint32_t*)&t2;
                    }
                    *(uint4*)(g_xbz + (size_t)m * 2048 + nb + q*8) = make_uint4(p[0],p[1],p[2],p[3]);
                } else {
                    int nbq = nb + q*8;
                    float4 x0 = *(const float4*)(xres + (size_t)m * 1024 + nbq);
                    float4 x1 = *(const float4*)(xres + (size_t)m * 1024 + nbq + 4);
                    *(float4*)(outp + (size_t)m * 1024 + nbq) =
                        make_float4(__uint_as_float(r32[q*8+0])+x0.x, __uint_as_float(r32[q*8+1])+x0.y,
                                    __uint_as_float(r32[q*8+2])+x0.z, __uint_as_float(r32[q*8+3])+x0.w);
                    *(float4*)(outp + (size_t)m * 1024 + nbq + 4) =
                        make_float4(__uint_as_float(r32[q*8+4])+x1.x, __uint_as_float(r32[q*8+5])+x1.y,
                                    __uint_as_float(r32[q*8+6])+x1.z, __uint_as_float(r32[q*8+7])+x1.w);
                }
            }
        }
    }
    __syncthreads();
    if (warp == 0) tc_dealloc(tmem, 256u);
    cluster_sync_();
}

// ---------------- non-cluster GEMM (r12 path): M256, blocking pipeline ----------------
// EPI 1: cols<128 -> fused scan-prep, cols>=128 -> g_projd; EPI 2: gated -> g_u
template<int EPI, int KDIM, int NTILE>
__global__ void __launch_bounds__(256, 1) gemm_tc(
    const __grid_constant__ CUtensorMap mA,
    const __grid_constant__ CUtensorMap mW,
    const float* __restrict__ aux0, const float* __restrict__ aux1,
    const float* __restrict__ aux2, float* __restrict__ outp)
{
    extern __shared__ __align__(1024) char smem_raw[];
    constexpr int NSC = KDIM / 64;
    constexpr int STAGE = 32768 + NTILE * 128;
    constexpr int NST = 3;
    constexpr uint32_t STBYTES = (uint32_t)STAGE;
    constexpr uint32_t IDESC = (1u<<4) | (1u<<7) | (1u<<10) | ((NTILE/8u)<<17) | (8u<<24);
    const int tid = threadIdx.x, lane = tid & 31, warp = tid >> 5;
    const int m0 = blockIdx.y * 256;
    const int n0 = blockIdx.x * NTILE;
    const uint32_t sbase = (uint32_t)__cvta_generic_to_shared(smem_raw);
    const uint32_t mb_wf = sbase + 16;
    const uint32_t mb_mm = sbase + 16 + 8*NST;

    if (warp == 0) tc_alloc(sbase, 512u);
    if (tid == 0){
        #pragma unroll
        for (int s = 0; s < NST; s++){ mbar_init(mb_wf + 8*s, 1); mbar_init(mb_mm + 8*s, 1); }
    }
    __syncthreads();
    uint32_t tmem;
    asm volatile("ld.shared.b32 %0, [%1];" : "=r"(tmem) : "r"(sbase));

    if (tid == 0){
        auto issue_load = [&](int j){
            int s = j % NST;
            uint32_t ab = sbase + 1024 + (uint32_t)s * STAGE;
            mbar_expect_tx(mb_wf + 8*s, STBYTES);
            tma2d(ab, (const void*)&mA, j*64, m0, mb_wf + 8*s);
            #pragma unroll
            for (int c = 0; c < NTILE; c += 64)
                tma2d(ab + 32768 + (uint32_t)c*128, (const void*)&mW, j*64, n0 + c, mb_wf + 8*s);
        };
        const int P = (NSC < NST) ? NSC : NST;
        for (int s = 0; s < P; s++) issue_load(s);
        for (int j = 0; j < NSC; j++){
            const int s = j % NST;
            const uint32_t par = (j / NST) & 1;
            mbar_wait(mb_wf + 8*s, par);
            uint32_t ab = sbase + 1024 + (uint32_t)s * STAGE;
            uint64_t a0d = sdesc(ab), a1d = sdesc(ab + 16384);
            uint64_t bd = sdesc(ab + 32768);
            #pragma unroll
            for (int ks = 0; ks < 4; ks++)
                mma_f16_ss(tmem, a0d + ks*2, bd + ks*2, IDESC, (j == 0 && ks == 0) ? 0u : 1u);
            #pragma unroll
            for (int ks = 0; ks < 4; ks++)
                mma_f16_ss(tmem + NTILE, a1d + ks*2, bd + ks*2, IDESC, (j == 0 && ks == 0) ? 0u : 1u);
            tc_commit(mb_mm + 8*s);
            if (j + NST < NSC){
                mbar_wait(mb_mm + 8*s, par);
                issue_load(j + NST);
            }
        }
        for (int s = 0; s < NST && s < NSC; s++){
            int lj = NSC - 1 - ((NSC - 1 - s) % NST);
            mbar_wait(mb_mm + 8*s, (uint32_t)((lj / NST) & 1));
        }
    }
    __syncthreads();
    tc_fence_after();

    {
        const int mhalf  = warp >> 2;
        const int rowgrp = warp & 3;
        const int m      = m0 + mhalf * 128 + rowgrp * 32 + lane;
        const uint32_t woff = (uint32_t)rowgrp << 21;
        const uint32_t tbase = tmem + (uint32_t)mhalf * NTILE + woff;
        float* spf = (float*)(smem_raw + 1024);
        constexpr int GPW = NTILE / 32;
        uint32_t bufs[2][32];
        ldtm32(tbase, bufs[0]);
        #pragma unroll
        for (int g = 0; g < GPW; g++){
            tc_wait_ld();
            if (g + 1 < GPW) ldtm32(tbase + (g+1)*32, bufs[(g+1) & 1]);
            const uint32_t* r32 = bufs[g & 1];
            const int nb = n0 + g * 32;
            #pragma unroll
            for (int q = 0; q < 4; q++){
                float v[8];
                #pragma unroll
                for (int i = 0; i < 8; i++) v[i] = __uint_as_float(r32[q*8 + i]);
                int nbq = nb + q*8;
                if (EPI == 1){
                    if (nbq < 128){
                        int tt = m - m0;
                        #pragma unroll
                        for (int i = 0; i < 8; i++) spf[tt*129 + nbq + i] = v[i];
                    } else {
                        uint32_t p[4];
                        #pragma unroll
                        for (int i = 0; i < 4; i++){
                            __nv_bfloat162 t2 = __floats2bfloat162_rn(v[2*i], v[2*i+1]);
                            p[i] = *(uint32_t*)&t2;
                        }
                        *(uint4*)(g_projd + (size_t)m * 1024 + (nbq - 128)) = make_uint4(p[0],p[1],p[2],p[3]);
                    }
                } else {
                    uint4 zz = *(const uint4*)(g_xbz + (size_t)m * 2048 + 1024 + nbq);
                    uint4 dd = *(const uint4*)(g_projd + (size_t)m * 1024 + nbq);
                    const uint32_t* zp = &zz.x;
                    const uint32_t* dp = &dd.x;
                    uint32_t p[4];
                    #pragma unroll
                    for (int i = 0; i < 4; i++){
                        __nv_bfloat162 z2 = *(__nv_bfloat162*)&zp[i];
                        __nv_bfloat162 d2 = *(__nv_bfloat162*)&dp[i];
                        float u0 = (v[2*i]   + aux0[nbq+2*i]   + aux1[nbq+2*i]   + __bfloat162float(d2.x))
                                 * siluf(__bfloat162float(z2.x));
                        float u1 = (v[2*i+1] + aux0[nbq+2*i+1] + aux1[nbq+2*i+1] + __bfloat162float(d2.y))
                                 * siluf(__bfloat162float(z2.y));
                        __nv_bfloat162 t2 = __floats2bfloat162_rn(u0, u1);
                        p[i] = *(uint32_t*)&t2;
                    }
                    *(uint4*)(g_u + (size_t)m * 1024 + nbq) = make_uint4(p[0],p[1],p[2],p[3]);
                }
            }
        }
        if (EPI == 1){
            __syncthreads();
            if (blockIdx.x == 0){
                const int bq = m0 >> 12;
                const int t0q = m0 & 4095;
                #pragma unroll
                for (int hi = 0; hi < 8; hi++){
                    const int h = warp * 8 + hi;
                    const float alog = -softplusf(aux0[h]);
                    const float bb = aux1[h];
                    const float dbh = aux2[h];
                    const size_t rowbase = (size_t)(bq * 64 + h) * 4096 + t0q;
                    #pragma unroll
                    for (int k = 0; k < 8; k++){
                        const int tt = lane + 32 * k;
                        const float p1 = spf[tt*129 + h];
                        const float p2 = spf[tt*129 + 64 + h];
                        const float delta = softplusf(p1 + dbh);
                        g_a [rowbase + tt] = delta * alog;
                        g_bu[rowbase + tt] = delta * (p2 + bb);
                    }
                }
            }
        }
    }
    __syncthreads();
    if (warp == 0) tc_dealloc(tmem, 512u);
}

// ---------------- host-side tensormaps ----------------
typedef CUresult (*PFN_encodeTiled)(CUtensorMap*, CUtensorMapDataType, cuuint32_t, void*,
                                    const cuuint64_t*, const cuuint64_t*, const cuuint32_t*,
                                    const cuuint32_t*, CUtensorMapInterleave, CUtensorMapSwizzle,
                                    CUtensorMapL2promotion, CUtensorMapFloatOOBfill);

static void make_map(PFN_encodeTiled enc, CUtensorMap* map, void* base,
                     unsigned long long inner, unsigned long long rows,
                     unsigned int box_inner, unsigned int box_rows){
    cuuint64_t dims[2]    = {inner, rows};
    cuuint64_t strides[1] = {inner * 2};
    cuuint32_t box[2]     = {box_inner, box_rows};
    cuuint32_t est[2]     = {1u, 1u};
    enc(map, CU_TENSOR_MAP_DATA_TYPE_BFLOAT16, 2, base, dims, strides, box, est,
        CU_TENSOR_MAP_INTERLEAVE_NONE, CU_TENSOR_MAP_SWIZZLE_128B,
        CU_TENSOR_MAP_L2_PROMOTION_L2_128B, CU_TENSOR_MAP_FLOAT_OOB_FILL_NONE);
}

// ---------------- launch ----------------
extern "C" void kernel_launch(void* const* d_in, const int* in_sizes, int n_in,
                              void* d_out, int out_size){
    const float* x      = (const float*)d_in[0];
    const float* norm_w = (const float*)d_in[1];
    const float* W1     = (const float*)d_in[2];
    const float* W2     = (const float*)d_in[3];
    const float* Wlast  = (const float*)d_in[4];
    const float* conv_w = (const float*)d_in[5];
    const float* conv_b = (const float*)d_in[6];
    const float* Ap     = (const float*)d_in[7];
    const float* Bw     = (const float*)d_in[8];
    const float* Bb     = (const float*)d_in[9];
    const float* Cw     = (const float*)d_in[10];
    const float* Cb     = (const float*)d_in[11];
    const float* Dw     = (const float*)d_in[12];
    const float* Db     = (const float*)d_in[13];
    const float* dwp    = (const float*)d_in[14];
    const float* dbp    = (const float*)d_in[15];
    float* out = (float*)d_out;

    PFN_encodeTiled enc = nullptr;
    cudaDriverEntryPointQueryResult qres;
    cudaGetDriverEntryPointByVersion("cuTensorMapEncodeTiled", (void**)&enc, 12000,
                                     cudaEnableDefault, &qres);
    void *pXn, *pXc, *pH, *pU, *pWa, *pWb, *pWc, *pWd;
    cudaGetSymbolAddress(&pXn, g_xn);
    cudaGetSymbolAddress(&pXc, g_xc);
    cudaGetSymbolAddress(&pH,  g_h);
    cudaGetSymbolAddress(&pU,  g_u);
    cudaGetSymbolAddress(&pWa, g_Wa);
    cudaGetSymbolAddress(&pWb, g_Wb);
    cudaGetSymbolAddress(&pWc, g_Wc);
    cudaGetSymbolAddress(&pWd, g_Wd);
    CUtensorMap mA0, mA1, mA2, mA3, mW0, mW1, mW2, mW3;
    make_map(enc, &mA0, pXn, 1024, 32768, 64, 128);   // M128 boxes
    make_map(enc, &mA1, pXc, 1024, 32768, 64, 256);
    make_map(enc, &mA2, pH,    64, 32768, 64, 256);
    make_map(enc, &mA3, pU,  1024, 32768, 64, 128);   // M128 boxes
    make_map(enc, &mW0, pWa, 1024,  2048, 64, 64);
    make_map(enc, &mW1, pWb, 1024,  1152, 64, 64);
    make_map(enc, &mW2, pWc,   64,  1024, 64, 64);
    make_map(enc, &mW3, pWd, 1024,  1024, 64, 64);

    const int SMC   = 1024 + 4*(16384 + 256*128);   // 197632 (M128, NST=4)
    const int SM256 = 1024 + 3*(32768 + 256*128);   // 197632
    const int SM192 = 1024 + 3*(32768 + 192*128);   // 173056
    cudaFuncSetAttribute((const void*)gemm_mc<0,1024,256>, cudaFuncAttributeMaxDynamicSharedMemorySize, SMC);
    cudaFuncSetAttribute((const void*)gemm_mc<3,1024,256>, cudaFuncAttributeMaxDynamicSharedMemorySize, SMC);
    cudaFuncSetAttribute((const void*)gemm_tc<1,1024,192>, cudaFuncAttributeMaxDynamicSharedMemorySize, SM192);
    cudaFuncSetAttribute((const void*)gemm_tc<2,64,256>,   cudaFuncAttributeMaxDynamicSharedMemorySize, SM256);

    convert_wa<<<8192, 256>>>(W1, W2);
    rmsnorm_kernel<<<32768, 256>>>(x, norm_w);
    convert_wrest<<<8960, 256>>>(dwp, Bw, Dw, Cw, Wlast);
    gemm_mc<0,1024,256><<<dim3(8, 256), 256, SMC>>>(mA0, mW0, nullptr, nullptr);
    conv_silu_kernel<<<8192, 256>>>(conv_w, conv_b);
    gemm_tc<1,1024,192><<<dim3(6, 128), 256, SM192>>>(mA1, mW1, Ap, Bb, dbp, nullptr);
    scan_kernel<<<512, 512>>>();
    htrans_kernel<<<512, 256>>>();
    gemm_tc<2,64,256><<<dim3(4, 128), 256, SM256>>>(mA2, mW2, Cb, Db, nullptr, nullptr);
    gemm_mc<3,1024,256><<<dim3(4, 256), 256, SMC>>>(mA3, mW3, (const float*)x, out);
}

// round 16
// speedup vs baseline: 1.0810x; 1.0810x over previous
#include <cuda_runtime.h>
#include <cuda.h>
#include <cuda_bf16.h>
#include <cstdint>
#include <math.h>

#define B_ 8
#define T_ 4096
#define D_ 1024
#define H_ 64
#define BT_ (B_*T_)   // 32768

#if defined(__CUDA_ARCH_FEAT_SM103_ALL) || defined(__CUDA_ARCH_FEAT_SM100_ALL)
#define HAS_TC 1
#else
#define HAS_TC 0
#endif

// ---------------- scratch ----------------
__device__ __nv_bfloat16 g_xn [(size_t)BT_*D_];
__device__ __nv_bfloat16 g_xbz[(size_t)BT_*2048];
__device__ __nv_bfloat16 g_xc [(size_t)BT_*D_];
__device__ __nv_bfloat16 g_projd[(size_t)BT_*1024];
__device__ float         g_a  [(size_t)512*4096];
__device__ float         g_bu [(size_t)512*4096];
__device__ __nv_bfloat16 g_h2 [(size_t)512*4096];
__device__ __nv_bfloat16 g_h  [(size_t)BT_*H_];
__device__ __nv_bfloat16 g_u  [(size_t)BT_*D_];
__device__ __nv_bfloat16 g_Wa [(size_t)2048*1024];
__device__ __nv_bfloat16 g_Wb [(size_t)1152*1024];
__device__ __nv_bfloat16 g_Wc [(size_t)1024*64];
__device__ __nv_bfloat16 g_Wd [(size_t)1024*1024];

// ---------------- helpers ----------------
__device__ __forceinline__ float siluf(float v){ return v / (1.f + __expf(-v)); }
__device__ __forceinline__ float softplusf(float v){ return (v > 20.f) ? v : log1pf(expf(v)); }
__device__ __forceinline__ float clipf(float v){ return fminf(fmaxf(v, -20.f), 20.f); }

__device__ __forceinline__ void mbar_wait(uint32_t addr, uint32_t parity){
    asm volatile(
        "{\n\t.reg .pred P;\n"
        "W_%=:\n\t"
        "mbarrier.try_wait.parity.shared.b64 P, [%0], %1;\n\t"
        "@P bra D_%=;\n\t"
        "bra W_%=;\n"
        "D_%=:\n\t}"
        :: "r"(addr), "r"(parity) : "memory");
}
__device__ __forceinline__ void mbar_init(uint32_t addr, uint32_t cnt){
    asm volatile("mbarrier.init.shared.b64 [%0], %1;" :: "r"(addr), "r"(cnt) : "memory");
}
__device__ __forceinline__ void mbar_expect_tx(uint32_t addr, uint32_t bytes){
    asm volatile("mbarrier.arrive.expect_tx.shared.b64 _, [%0], %1;" :: "r"(addr), "r"(bytes) : "memory");
}
__device__ __forceinline__ void tma2d(uint32_t dst, const void* map, int x, int y, uint32_t mbar){
#if HAS_TC
    asm volatile(
        "cp.async.bulk.tensor.2d.shared::cta.global.tile.mbarrier::complete_tx::bytes "
        "[%0], [%1, {%2, %3}], [%4];"
        :: "r"(dst), "l"(map), "r"(x), "r"(y), "r"(mbar) : "memory");
#endif
}
__device__ __forceinline__ uint64_t sdesc(uint32_t a){
    return ((uint64_t)2 << 61) | ((uint64_t)1 << 46) | ((uint64_t)64 << 32)
         | ((uint64_t)1 << 16) | ((a >> 4) & 0x3FFF);
}
__device__ __forceinline__ void mma_f16_ss(uint32_t dt, uint64_t ad, uint64_t bd,
                                           uint32_t idesc, uint32_t en){
#if HAS_TC
    asm volatile(
        "{\n\t.reg .pred p;\n\t"
        "setp.ne.u32 p, %5, 0;\n\t"
        "tcgen05.mma.cta_group::1.kind::f16 [%0], %1, %2, %3, {%4,%4,%4,%4}, p;\n\t}"
        :: "r"(dt), "l"(ad), "l"(bd), "r"(idesc), "r"(0u), "r"(en) : "memory");
#endif
}
__device__ __forceinline__ void ldtm32(uint32_t addr, uint32_t* r){
#if HAS_TC
    asm volatile(
        "tcgen05.ld.sync.aligned.32x32b.x32.b32 "
        "{%0,%1,%2,%3,%4,%5,%6,%7,%8,%9,%10,%11,%12,%13,%14,%15,"
        "%16,%17,%18,%19,%20,%21,%22,%23,%24,%25,%26,%27,%28,%29,%30,%31}, [%32];"
        : "=r"(r[0]),"=r"(r[1]),"=r"(r[2]),"=r"(r[3]),"=r"(r[4]),"=r"(r[5]),"=r"(r[6]),"=r"(r[7]),
          "=r"(r[8]),"=r"(r[9]),"=r"(r[10]),"=r"(r[11]),"=r"(r[12]),"=r"(r[13]),"=r"(r[14]),"=r"(r[15]),
          "=r"(r[16]),"=r"(r[17]),"=r"(r[18]),"=r"(r[19]),"=r"(r[20]),"=r"(r[21]),"=r"(r[22]),"=r"(r[23]),
          "=r"(r[24]),"=r"(r[25]),"=r"(r[26]),"=r"(r[27]),"=r"(r[28]),"=r"(r[29]),"=r"(r[30]),"=r"(r[31])
        : "r"(addr));
#else
    #pragma unroll
    for (int i = 0; i < 32; i++) r[i] = 0u;
    (void)addr;
#endif
}
__device__ __forceinline__ void tc_alloc(uint32_t smem_addr, uint32_t ncols){
#if HAS_TC
    asm volatile("tcgen05.alloc.cta_group::1.sync.aligned.shared::cta.b32 [%0], %1;"
                 :: "r"(smem_addr), "r"(ncols) : "memory");
#endif
}
__device__ __forceinline__ void tc_dealloc(uint32_t tmem, uint32_t ncols){
#if HAS_TC
    asm volatile("tcgen05.relinquish_alloc_permit.cta_group::1.sync.aligned;");
    asm volatile("tcgen05.dealloc.cta_group::1.sync.aligned.b32 %0, %1;" :: "r"(tmem), "r"(ncols));
#endif
}
__device__ __forceinline__ void tc_commit(uint32_t mbar){
#if HAS_TC
    asm volatile("tcgen05.commit.cta_group::1.mbarrier::arrive::one.shared::cluster.b64 [%0];"
                 :: "r"(mbar) : "memory");
#endif
}
__device__ __forceinline__ void tc_fence_after(){
#if HAS_TC
    asm volatile("tcgen05.fence::after_thread_sync;" ::: "memory");
#endif
}
__device__ __forceinline__ void tc_wait_ld(){
#if HAS_TC
    asm volatile("tcgen05.wait::ld.sync.aligned;" ::: "memory");
#endif
}

// ---------------- weight conversion (split so gemm0 lands in ncu capture slot) ----------------
__global__ void convert_wa(const float* __restrict__ W1, const float* __restrict__ W2){
    int i = blockIdx.x * blockDim.x + threadIdx.x;
    g_Wa[i] = __float2bfloat16(i < 1048576 ? W1[i] : W2[i - 1048576]);
}
__global__ void convert_wrest(const float* __restrict__ dwp, const float* __restrict__ Bwp,
                              const float* __restrict__ Dwp, const float* __restrict__ Cwp,
                              const float* __restrict__ Wlastp){
    int i = blockIdx.x * blockDim.x + threadIdx.x;
    const int NWb = 1152*1024, NWc = 1024*64, NWd = 1024*1024;
    if (i < NWb){
        float v = (i < 65536) ? dwp[i] : (i < 131072) ? Bwp[i - 65536] : Dwp[i - 131072];
        g_Wb[i] = __float2bfloat16(v);
    } else if (i < NWb + NWc){
        g_Wc[i - NWb] = __float2bfloat16(Cwp[i - NWb]);
    } else if (i < NWb + NWc + NWd){
        g_Wd[i - NWb - NWc] = __float2bfloat16(Wlastp[i - NWb - NWc]);
    }
}

// ---------------- RMSNorm ----------------
__global__ void rmsnorm_kernel(const float* __restrict__ x, const float* __restrict__ w){
    __shared__ float ws[8];
    int m = blockIdx.x, tid = threadIdx.x;
    float4 v = ((const float4*)(x + (size_t)m * D_))[tid];
    float ss = v.x*v.x + v.y*v.y + v.z*v.z + v.w*v.w;
    #pragma unroll
    for (int d = 16; d; d >>= 1) ss += __shfl_xor_sync(0xffffffffu, ss, d);
    if ((tid & 31) == 0) ws[tid >> 5] = ss;
    __syncthreads();
    if (tid == 0){ float s = 0.f; for (int i = 0; i < 8; i++) s += ws[i]; ws[0] = s; }
    __syncthreads();
    float scale = rsqrtf(ws[0] * (1.f / D_) + 1.1920928955078125e-07f);
    float4 wv = ((const float4*)w)[tid];
    __nv_bfloat162 p0 = __floats2bfloat162_rn(v.x*scale*wv.x, v.y*scale*wv.y);
    __nv_bfloat162 p1 = __floats2bfloat162_rn(v.z*scale*wv.z, v.w*scale*wv.w);
    __nv_bfloat162* dst = (__nv_bfloat162*)(g_xn + (size_t)m * D_) + tid * 2;
    dst[0] = p0; dst[1] = p1;
}

// ---------------- causal depthwise conv (k=3) + SiLU; 8 t per thread ----------------
__global__ void conv_silu_kernel(const float* __restrict__ conv_w, const float* __restrict__ conv_b){
    int idx = blockIdx.x * blockDim.x + threadIdx.x;
    int d2 = idx & 511;
    int rest = idx >> 9;
    int t8 = (rest & 511) * 8;
    int b = rest >> 9;
    int d = d2 * 2;
    __nv_bfloat162 zero2; zero2.x = __float2bfloat16(0.f); zero2.y = __float2bfloat16(0.f);
    __nv_bfloat162 v[10];
    #pragma unroll
    for (int i = 0; i < 10; i++){
        int t = t8 - 2 + i;
        v[i] = (t >= 0) ? *(const __nv_bfloat162*)(g_xbz + ((size_t)b*T_ + t)*2048 + d) : zero2;
    }
    float w00 = conv_w[d*3+0], w01 = conv_w[d*3+1], w02 = conv_w[d*3+2];
    float w10 = conv_w[d*3+3], w11 = conv_w[d*3+4], w12 = conv_w[d*3+5];
    float b0 = conv_b[d], b1 = conv_b[d+1];
    #pragma unroll
    for (int k = 0; k < 8; k++){
        float r0 = __bfloat162float(v[k].x)*w00 + __bfloat162float(v[k+1].x)*w01
                 + __bfloat162float(v[k+2].x)*w02 + b0;
        float r1 = __bfloat162float(v[k].y)*w10 + __bfloat162float(v[k+1].y)*w11
                 + __bfloat162float(v[k+2].y)*w12 + b1;
        *(__nv_bfloat162*)(g_xc + ((size_t)b*T_ + t8 + k)*1024 + d) =
            __floats2bfloat162_rn(siluf(r0), siluf(r1));
    }
}

// ---------------- block-parallel scan ----------------
__device__ __forceinline__ float block_excl_prefix(float total, float* wsum, int tid){
    __syncthreads();
    int lane = tid & 31, wid = tid >> 5;
    float v = total;
    #pragma unroll
    for (int d = 1; d < 32; d <<= 1){
        float o = __shfl_up_sync(0xffffffffu, v, d);
        if (lane >= d) v += o;
    }
    if (lane == 31) wsum[wid] = v;
    __syncthreads();
    if (tid == 0){
        float s = 0.f;
        for (int i = 0; i < 16; i++){ float t = wsum[i]; wsum[i] = s; s += t; }
    }
    __syncthreads();
    return wsum[wid] + v - total;
}

__global__ void scan_kernel(){
    __shared__ float wsum[16];
    int bh = blockIdx.x;
    int tid = threadIdx.x;
    size_t base = (size_t)bh * 4096 + tid * 8;
    float av[8], bv[8], ev[8], cv[8];
    {
        float4 a0 = *(const float4*)(g_a + base);
        float4 a1 = *(const float4*)(g_a + base + 4);
        av[0]=a0.x; av[1]=a0.y; av[2]=a0.z; av[3]=a0.w;
        av[4]=a1.x; av[5]=a1.y; av[6]=a1.z; av[7]=a1.w;
        float4 b0 = *(const float4*)(g_bu + base);
        float4 b1 = *(const float4*)(g_bu + base + 4);
        bv[0]=b0.x; bv[1]=b0.y; bv[2]=b0.z; bv[3]=b0.w;
        bv[4]=b1.x; bv[5]=b1.y; bv[6]=b1.z; bv[7]=b1.w;
    }
    float s = 0.f;
    #pragma unroll
    for (int i = 0; i < 8; i++){ s += av[i]; av[i] = s; }
    float pa = block_excl_prefix(av[7], wsum, tid);
    #pragma unroll
    for (int i = 0; i < 8; i++){
        float S = pa + av[i];
        float Sprev = pa + (i ? av[i-1] : 0.f);
        ev[i] = expf(clipf(S));
        cv[i] = bv[i] * expf(-clipf(Sprev));
    }
    s = 0.f;
    #pragma unroll
    for (int i = 0; i < 8; i++){ s += cv[i]; cv[i] = s; }
    float pb = block_excl_prefix(cv[7], wsum, tid);
    uint32_t p[4];
    #pragma unroll
    for (int i = 0; i < 4; i++){
        __nv_bfloat162 t2 = __floats2bfloat162_rn(ev[2*i] * (pb + cv[2*i]),
                                                  ev[2*i+1] * (pb + cv[2*i+1]));
        p[i] = *(uint32_t*)&t2;
    }
    *(uint4*)(g_h2 + base) = make_uint4(p[0], p[1], p[2], p[3]);
}

// ---------------- [bh][t] -> token-major transpose ----------------
__global__ void htrans_kernel(){
    __shared__ __nv_bfloat16 sm[64][80];
    int blk = blockIdx.x;
    int b = blk >> 6;
    int t0 = (blk & 63) << 6;
    for (int i = threadIdx.x; i < 512; i += 256){
        int h = i >> 3, c = i & 7;
        uint4 v = *(const uint4*)(g_h2 + ((size_t)(b*64 + h))*4096 + t0 + c*8);
        __nv_bfloat16 tmp[8];
        *(uint4*)tmp = v;
        #pragma unroll
        for (int q = 0; q < 8; q++) sm[c*8 + q][h] = tmp[q];
    }
    __syncthreads();
    for (int i = threadIdx.x; i < 512; i += 256){
        int t = i >> 3, hc = i & 7;
        uint4 v = *(uint4*)&sm[t][hc*8];
        *(uint4*)(g_h + ((size_t)(b*T_ + t0 + t))*64 + hc*8) = v;
    }
}

// ---------------- tcgen05 GEMM: M256 x N<=256, TMA, warp-specialized producer/consumer ----------------
// EPI 0: bf16 -> g_xbz; EPI 1: cols<128 -> fused scan-prep, cols>=128 -> g_projd;
// EPI 2: gated -> g_u; EPI 3: +res -> out
template<int EPI, int KDIM, int NTILE>
__global__ void __launch_bounds__(256, 1) gemm_tc(
    const __grid_constant__ CUtensorMap mA,
    const __grid_constant__ CUtensorMap mW,
    const float* __restrict__ aux0, const float* __restrict__ aux1,
    const float* __restrict__ aux2, float* __restrict__ outp)
{
    extern __shared__ __align__(1024) char smem_raw[];
    constexpr int NSC = KDIM / 64;
    constexpr int STAGE = 32768 + NTILE * 128;        // A(256x64) 32KB + W(NTILEx64)
    constexpr int NST = 3;
    constexpr uint32_t STBYTES = (uint32_t)STAGE;
    constexpr uint32_t IDESC = (1u<<4) | (1u<<7) | (1u<<10) | ((NTILE/8u)<<17) | (8u<<24);
    const int tid = threadIdx.x, lane = tid & 31, warp = tid >> 5;
    const int m0 = blockIdx.y * 256;
    const int n0 = blockIdx.x * NTILE;
    const uint32_t sbase = (uint32_t)__cvta_generic_to_shared(smem_raw);
    const uint32_t mb_wf = sbase + 16;
    const uint32_t mb_mm = sbase + 16 + 8*NST;

    if (warp == 0) tc_alloc(sbase, 512u);
    if (tid == 0){
        #pragma unroll
        for (int s = 0; s < NST; s++){ mbar_init(mb_wf + 8*s, 1); mbar_init(mb_mm + 8*s, 1); }
    }
    __syncthreads();
    uint32_t tmem;
    asm volatile("ld.shared.b32 %0, [%1];" : "=r"(tmem) : "r"(sbase));

    // -------- producer: issue loads as soon as a slot's MMA commit lands --------
    if (tid == 32){
        for (int j = 0; j < NSC; j++){
            const int s = j % NST;
            if (j >= NST) mbar_wait(mb_mm + 8*s, ((j - NST) / NST) & 1);
            uint32_t ab = sbase + 1024 + (uint32_t)s * STAGE;
            mbar_expect_tx(mb_wf + 8*s, STBYTES);
            tma2d(ab, (const void*)&mA, j*64, m0, mb_wf + 8*s);
            #pragma unroll
            for (int c = 0; c < NTILE; c += 64)
                tma2d(ab + 32768 + (uint32_t)c*128, (const void*)&mW, j*64, n0 + c, mb_wf + 8*s);
        }
    }
    // -------- consumer: wait tile, dispatch MMAs, commit --------
    if (tid == 0){
        for (int j = 0; j < NSC; j++){
            const int s = j % NST;
            mbar_wait(mb_wf + 8*s, (j / NST) & 1);
            uint32_t ab = sbase + 1024 + (uint32_t)s * STAGE;
            uint64_t a0d = sdesc(ab), a1d = sdesc(ab + 16384);
            uint64_t bd = sdesc(ab + 32768);
            #pragma unroll
            for (int ks = 0; ks < 4; ks++)
                mma_f16_ss(tmem, a0d + ks*2, bd + ks*2, IDESC, (j == 0 && ks == 0) ? 0u : 1u);
            #pragma unroll
            for (int ks = 0; ks < 4; ks++)
                mma_f16_ss(tmem + NTILE, a1d + ks*2, bd + ks*2, IDESC, (j == 0 && ks == 0) ? 0u : 1u);
            tc_commit(mb_mm + 8*s);
        }
        // in-order tensor pipe: last stage's commit implies all MMAs done
        mbar_wait(mb_mm + 8*((NSC-1) % NST), ((NSC-1) / NST) & 1);
    }
    __syncthreads();
    tc_fence_after();

    // ---- direct TMEM -> global epilogue: 8 warps over 256 rows x NTILE cols ----
    {
        const int mhalf  = warp >> 2;
        const int rowgrp = warp & 3;
        const int m      = m0 + mhalf * 128 + rowgrp * 32 + lane;
        const uint32_t woff = (uint32_t)rowgrp << 21;
        const uint32_t tbase = tmem + (uint32_t)mhalf * NTILE + woff;
        float* spf = (float*)(smem_raw + 1024);        // reused stage smem (EPI==1 scan-prep)
        constexpr int GPW = NTILE / 32;
        uint32_t bufs[2][32];
        ldtm32(tbase, bufs[0]);
        #pragma unroll
        for (int g = 0; g < GPW; g++){
            tc_wait_ld();
            if (g + 1 < GPW) ldtm32(tbase + (g+1)*32, bufs[(g+1) & 1]);
            const uint32_t* r32 = bufs[g & 1];
            const int nb = n0 + g * 32;
            #pragma unroll
            for (int q = 0; q < 4; q++){
                float v[8];
                #pragma unroll
                for (int i = 0; i < 8; i++) v[i] = __uint_as_float(r32[q*8 + i]);
                int nbq = nb + q*8;
                if (EPI == 0){
                    uint32_t p[4];
                    #pragma unroll
                    for (int i = 0; i < 4; i++){
                        __nv_bfloat162 t2 = __floats2bfloat162_rn(v[2*i], v[2*i+1]);
                        p[i] = *(uint32_t*)&t2;
                    }
                    *(uint4*)(g_xbz + (size_t)m * 2048 + nbq) = make_uint4(p[0],p[1],p[2],p[3]);
                } else if (EPI == 1){
                    if (nbq < 128){
                        int tt = m - m0;
                        #pragma unroll
                        for (int i = 0; i < 8; i++) spf[tt*129 + nbq + i] = v[i];
                    } else {
                        uint32_t p[4];
                        #pragma unroll
                        for (int i = 0; i < 4; i++){
                            __nv_bfloat162 t2 = __floats2bfloat162_rn(v[2*i], v[2*i+1]);
                            p[i] = *(uint32_t*)&t2;
                        }
                        *(uint4*)(g_projd + (size_t)m * 1024 + (nbq - 128)) = make_uint4(p[0],p[1],p[2],p[3]);
                    }
                } else if (EPI == 2){
                    uint4 zz = *(const uint4*)(g_xbz + (size_t)m * 2048 + 1024 + nbq);
                    uint4 dd = *(const uint4*)(g_projd + (size_t)m * 1024 + nbq);
                    const uint32_t* zp = &zz.x;
                    const uint32_t* dp = &dd.x;
                    uint32_t p[4];
                    #pragma unroll
                    for (int i = 0; i < 4; i++){
                        __nv_bfloat162 z2 = *(__nv_bfloat162*)&zp[i];
                        __nv_bfloat162 d2 = *(__nv_bfloat162*)&dp[i];
                        float u0 = (v[2*i]   + aux0[nbq+2*i]   + aux1[nbq+2*i]   + __bfloat162float(d2.x))
                                 * siluf(__bfloat162float(z2.x));
                        float u1 = (v[2*i+1] + aux0[nbq+2*i+1] + aux1[nbq+2*i+1] + __bfloat162float(d2.y))
                                 * siluf(__bfloat162float(z2.y));
                        __nv_bfloat162 t2 = __floats2bfloat162_rn(u0, u1);
                        p[i] = *(uint32_t*)&t2;
                    }
                    *(uint4*)(g_u + (size_t)m * 1024 + nbq) = make_uint4(p[0],p[1],p[2],p[3]);
                } else {
                    const float* xres = aux2;
                    float4 x0 = *(const float4*)(xres + (size_t)m * 1024 + nbq);
                    float4 x1 = *(const float4*)(xres + (size_t)m * 1024 + nbq + 4);
                    *(float4*)(outp + (size_t)m * 1024 + nbq) =
                        make_float4(v[0]+x0.x, v[1]+x0.y, v[2]+x0.z, v[3]+x0.w);
                    *(float4*)(outp + (size_t)m * 1024 + nbq + 4) =
                        make_float4(v[4]+x1.x, v[5]+x1.y, v[6]+x1.z, v[7]+x1.w);
                }
            }
        }
        // ---- EPI 1 phase 2: fused scan-prep from smem (block x==0 owns cols 0..127) ----
        if (EPI == 1){
            __syncthreads();
            if (blockIdx.x == 0){
                const int bq = m0 >> 12;
                const int t0q = m0 & 4095;
                #pragma unroll
                for (int hi = 0; hi < 8; hi++){
                    const int h = warp * 8 + hi;
                    const float alog = -softplusf(aux0[h]);
                    const float bb = aux1[h];
                    const float dbh = aux2[h];
                    const size_t rowbase = (size_t)(bq * 64 + h) * 4096 + t0q;
                    #pragma unroll
                    for (int k = 0; k < 8; k++){
                        const int tt = lane + 32 * k;
                        const float p1 = spf[tt*129 + h];
                        const float p2 = spf[tt*129 + 64 + h];
                        const float delta = softplusf(p1 + dbh);
                        g_a [rowbase + tt] = delta * alog;
                        g_bu[rowbase + tt] = delta * (p2 + bb);
                    }
                }
            }
        }
    }
    __syncthreads();
    if (warp == 0) tc_dealloc(tmem, 512u);
}

// ---------------- host-side tensormaps ----------------
typedef CUresult (*PFN_encodeTiled)(CUtensorMap*, CUtensorMapDataType, cuuint32_t, void*,
                                    const cuuint64_t*, const cuuint64_t*, const cuuint32_t*,
                                    const cuuint32_t*, CUtensorMapInterleave, CUtensorMapSwizzle,
                                    CUtensorMapL2promotion, CUtensorMapFloatOOBfill);

static void make_map(PFN_encodeTiled enc, CUtensorMap* map, void* base,
                     unsigned long long inner, unsigned long long rows,
                     unsigned int box_inner, unsigned int box_rows){
    cuuint64_t dims[2]    = {inner, rows};
    cuuint64_t strides[1] = {inner * 2};
    cuuint32_t box[2]     = {box_inner, box_rows};
    cuuint32_t est[2]     = {1u, 1u};
    enc(map, CU_TENSOR_MAP_DATA_TYPE_BFLOAT16, 2, base, dims, strides, box, est,
        CU_TENSOR_MAP_INTERLEAVE_NONE, CU_TENSOR_MAP_SWIZZLE_128B,
        CU_TENSOR_MAP_L2_PROMOTION_L2_128B, CU_TENSOR_MAP_FLOAT_OOB_FILL_NONE);
}

// ---------------- launch ----------------
extern "C" void kernel_launch(void* const* d_in, const int* in_sizes, int n_in,
                              void* d_out, int out_size){
    const float* x      = (const float*)d_in[0];
    const float* norm_w = (const float*)d_in[1];
    const float* W1     = (const float*)d_in[2];
    const float* W2     = (const float*)d_in[3];
    const float* Wlast  = (const float*)d_in[4];
    const float* conv_w = (const float*)d_in[5];
    const float* conv_b = (const float*)d_in[6];
    const float* Ap     = (const float*)d_in[7];
    const float* Bw     = (const float*)d_in[8];
    const float* Bb     = (const float*)d_in[9];
    const float* Cw     = (const float*)d_in[10];
    const float* Cb     = (const float*)d_in[11];
    const float* Dw     = (const float*)d_in[12];
    const float* Db     = (const float*)d_in[13];
    const float* dwp    = (const float*)d_in[14];
    const float* dbp    = (const float*)d_in[15];
    float* out = (float*)d_out;

    PFN_encodeTiled enc = nullptr;
    cudaDriverEntryPointQueryResult qres;
    cudaGetDriverEntryPointByVersion("cuTensorMapEncodeTiled", (void**)&enc, 12000,
                                     cudaEnableDefault, &qres);
    void *pXn, *pXc, *pH, *pU, *pWa, *pWb, *pWc, *pWd;
    cudaGetSymbolAddress(&pXn, g_xn);
    cudaGetSymbolAddress(&pXc, g_xc);
    cudaGetSymbolAddress(&pH,  g_h);
    cudaGetSymbolAddress(&pU,  g_u);
    cudaGetSymbolAddress(&pWa, g_Wa);
    cudaGetSymbolAddress(&pWb, g_Wb);
    cudaGetSymbolAddress(&pWc, g_Wc);
    cudaGetSymbolAddress(&pWd, g_Wd);
    CUtensorMap mA0, mA1, mA2, mA3, mW0, mW1, mW2, mW3;
    make_map(enc, &mA0, pXn, 1024, 32768, 64, 256);
    make_map(enc, &mA1, pXc, 1024, 32768, 64, 256);
    make_map(enc, &mA2, pH,    64, 32768, 64, 256);
    make_map(enc, &mA3, pU,  1024, 32768, 64, 256);
    make_map(enc, &mW0, pWa, 1024,  2048, 64, 64);
    make_map(enc, &mW1, pWb, 1024,  1152, 64, 64);
    make_map(enc, &mW2, pWc,   64,  1024, 64, 64);
    make_map(enc, &mW3, pWd, 1024,  1024, 64, 64);

    const int SM256 = 1024 + 3*(32768 + 256*128);   // 197632
    const int SM192 = 1024 + 3*(32768 + 192*128);   // 173056
    cudaFuncSetAttribute((const void*)gemm_tc<0,1024,256>, cudaFuncAttributeMaxDynamicSharedMemorySize, SM256);
    cudaFuncSetAttribute((const void*)gemm_tc<1,1024,192>, cudaFuncAttributeMaxDynamicSharedMemorySize, SM192);
    cudaFuncSetAttribute((const void*)gemm_tc<2,64,256>,   cudaFuncAttributeMaxDynamicSharedMemorySize, SM256);
    cudaFuncSetAttribute((const void*)gemm_tc<3,1024,256>, cudaFuncAttributeMaxDynamicSharedMemorySize, SM256);

    convert_wa<<<8192, 256>>>(W1, W2);
    rmsnorm_kernel<<<32768, 256>>>(x, norm_w);
    convert_wrest<<<8960, 256>>>(dwp, Bw, Dw, Cw, Wlast);
    gemm_tc<0,1024,256><<<dim3(8, 128), 256, SM256>>>(mA0, mW0, nullptr, nullptr, nullptr, nullptr);
    conv_silu_kernel<<<8192, 256>>>(conv_w, conv_b);
    gemm_tc<1,1024,192><<<dim3(6, 128), 256, SM192>>>(mA1, mW1, Ap, Bb, dbp, nullptr);
    scan_kernel<<<512, 512>>>();
    htrans_kernel<<<512, 256>>>();
    gemm_tc<2,64,256><<<dim3(4, 128), 256, SM256>>>(mA2, mW2, Cb, Db, nullptr, nullptr);
    gemm_tc<3,1024,256><<<dim3(4, 128), 256, SM256>>>(mA3, mW3, nullptr, nullptr, (const float*)x, out);
}